// round 4
// baseline (speedup 1.0000x reference)
#include <cuda_runtime.h>
#include <cstddef>

// Problem constants (fixed shapes per reference)
#define D_DIM   256     // feature dim
#define K_CODES 1024    // codebook size
#define P_PER_B 1024    // 32*32 points per batch
#define N_BATCH 64
#define N_PTS   (N_BATCH * P_PER_B)   // 65536
#define TM      128     // point tile
#define TN      128     // code tile (x8 inside CTA)
#define TK      16      // k-slice

// scratch (allocation-free rule: __device__ globals)
__device__ float g_e2[K_CODES];
__device__ float g_zz[N_PTS];

// ---------------------------------------------------------------------------
// e2[k] = sum_d emb[k,d]^2   (one warp per code)
// ---------------------------------------------------------------------------
__global__ void e2_kernel(const float* __restrict__ emb) {
    int k = blockIdx.x;
    int lane = threadIdx.x;              // 32 threads
    const float* row = emb + (size_t)k * D_DIM;
    float s = 0.f;
    #pragma unroll
    for (int j = 0; j < D_DIM / 32; ++j) {
        float v = row[lane + 32 * j];
        s = __fmaf_rn(v, v, s);
    }
    #pragma unroll
    for (int o = 16; o > 0; o >>= 1) s += __shfl_xor_sync(0xffffffffu, s, o);
    if (lane == 0) g_e2[k] = s;
}

// ---------------------------------------------------------------------------
// zz[n] = sum_d z[b,d,p]^2   (one thread per point; coalesced over p)
// ---------------------------------------------------------------------------
__global__ void zz_kernel(const float* __restrict__ z) {
    int n = blockIdx.x * blockDim.x + threadIdx.x;   // 0..65535
    int b = n >> 10;
    int p = n & 1023;
    const float* zp = z + (size_t)b * D_DIM * P_PER_B + p;
    float s = 0.f;
    #pragma unroll 8
    for (int d = 0; d < D_DIM; ++d) {
        float v = zp[(size_t)d * P_PER_B];
        s = __fmaf_rn(v, v, s);
    }
    g_zz[n] = s;
}

// ---------------------------------------------------------------------------
// Main: per-CTA 128 points x ALL 1024 codes, fp32 GEMM + running argmin on
// the reference-quantized distance  q = fl( fma(-2,dot,zz) + e2 ).
// Grid (8 point-tiles, 64 batches), 256 threads, 8x8 micro-tile.
// z is NCHW = [b][d][point], points contiguous -> coalesced A loads.
// OUTPUT: indices written as FLOAT (harness output dtype is float32).
// ---------------------------------------------------------------------------
__global__ __launch_bounds__(256)
void vq_argmin_kernel(const float* __restrict__ z,
                      const float* __restrict__ emb,
                      float* __restrict__ out) {
    __shared__ float As[TK][TM];   // [k-slice][point]
    __shared__ float Bs[TK][TN];   // [k-slice][code]

    const int tid = threadIdx.x;
    const int tx  = tid & 15;      // code group (8 codes)
    const int ty  = tid >> 4;      // point group (8 points)
    const int b   = blockIdx.y;
    const int m0  = blockIdx.x * TM;

    const float* zb = z + (size_t)b * D_DIM * P_PER_B + m0;

    // per-point ||z||^2 (same value for all codes of a row)
    float zzv[8];
    #pragma unroll
    for (int i = 0; i < 8; ++i)
        zzv[i] = g_zz[b * P_PER_B + m0 + ty * 8 + i];

    float bestV[8];
    int   bestI[8];
    #pragma unroll
    for (int i = 0; i < 8; ++i) { bestV[i] = 3.4e38f; bestI[i] = 0; }

    for (int nt = 0; nt < K_CODES / TN; ++nt) {
        const int n0 = nt * TN;

        float acc[8][8];
        #pragma unroll
        for (int i = 0; i < 8; ++i)
            #pragma unroll
            for (int j = 0; j < 8; ++j) acc[i][j] = 0.f;

        for (int kt = 0; kt < D_DIM / TK; ++kt) {
            __syncthreads();   // previous iter's smem reads done
            // ---- A tile: 16 k-rows x 128 points = 512 float4
            #pragma unroll
            for (int r = 0; r < 2; ++r) {
                int q  = tid + r * 256;
                int kk = q >> 5;          // 0..15
                int m4 = q & 31;          // float4 within row
                float4 v = *reinterpret_cast<const float4*>(
                    zb + (size_t)(kt * TK + kk) * P_PER_B + m4 * 4);
                *reinterpret_cast<float4*>(&As[kk][m4 * 4]) = v;
            }
            // ---- B tile: 128 codes x 16 d, transpose into [kk][n]
            #pragma unroll
            for (int r = 0; r < 2; ++r) {
                int q = tid + r * 256;
                int n = q >> 2;           // 0..127
                int c = q & 3;            // float4 chunk of the 16 d's
                float4 v = *reinterpret_cast<const float4*>(
                    emb + (size_t)(n0 + n) * D_DIM + kt * TK + c * 4);
                Bs[c * 4 + 0][n] = v.x;
                Bs[c * 4 + 1][n] = v.y;
                Bs[c * 4 + 2][n] = v.z;
                Bs[c * 4 + 3][n] = v.w;
            }
            __syncthreads();
            // ---- FFMA core
            #pragma unroll
            for (int kk = 0; kk < TK; ++kk) {
                float a[8], bb[8];
                *reinterpret_cast<float4*>(&a[0]) =
                    *reinterpret_cast<const float4*>(&As[kk][ty * 8]);
                *reinterpret_cast<float4*>(&a[4]) =
                    *reinterpret_cast<const float4*>(&As[kk][ty * 8 + 4]);
                *reinterpret_cast<float4*>(&bb[0]) =
                    *reinterpret_cast<const float4*>(&Bs[kk][tx * 8]);
                *reinterpret_cast<float4*>(&bb[4]) =
                    *reinterpret_cast<const float4*>(&Bs[kk][tx * 8 + 4]);
                #pragma unroll
                for (int i = 0; i < 8; ++i)
                    #pragma unroll
                    for (int j = 0; j < 8; ++j)
                        acc[i][j] += a[i] * bb[j];
            }
        }

        // ---- epilogue: reference-quantized distance + running argmin
        float e2v[8];
        #pragma unroll
        for (int j = 0; j < 8; ++j)
            e2v[j] = g_e2[n0 + tx * 8 + j];

        #pragma unroll
        for (int i = 0; i < 8; ++i) {
            float bv = bestV[i]; int bi = bestI[i];
            #pragma unroll
            for (int j = 0; j < 8; ++j) {
                // q = fl( fl(zz - 2*dot) + e2 ); fma(-2,dot,zz) == fl(zz - fl(2*dot))
                float t   = __fmaf_rn(-2.f, acc[i][j], zzv[i]);
                float val = __fadd_rn(t, e2v[j]);
                int   idx = n0 + tx * 8 + j;
                // ascending idx scan + strict < == first-min tie-break (jnp.argmin)
                if (val < bv) { bv = val; bi = idx; }
            }
            bestV[i] = bv; bestI[i] = bi;
        }
    }

    // ---- cross-lane argmin over the 16 tx-lanes sharing these 8 points.
    // Warp = two 16-lane halves with constant ty; xor offsets < 16 stay in-half.
    #pragma unroll
    for (int i = 0; i < 8; ++i) {
        float v = bestV[i]; int idx = bestI[i];
        #pragma unroll
        for (int o = 8; o > 0; o >>= 1) {
            float v2 = __shfl_xor_sync(0xffffffffu, v,   o);
            int   i2 = __shfl_xor_sync(0xffffffffu, idx, o);
            if (v2 < v || (v2 == v && i2 < idx)) { v = v2; idx = i2; }
        }
        bestV[i] = v; bestI[i] = idx;
    }

    if (tx == 0) {
        #pragma unroll
        for (int i = 0; i < 8; ++i)
            out[(size_t)b * P_PER_B + m0 + ty * 8 + i] = (float)bestI[i];
    }
}

// ---------------------------------------------------------------------------
extern "C" void kernel_launch(void* const* d_in, const int* in_sizes, int n_in,
                              void* d_out, int out_size) {
    // Identify inputs by size — robust to metadata ordering.
    // z_e_x: 64*256*32*32 = 16,777,216 floats; emb: 1024*256 = 262,144 floats.
    const float* z   = (const float*)d_in[0];
    const float* emb = (const float*)d_in[1];
    if (n_in >= 2 && in_sizes[0] == K_CODES * D_DIM) {
        emb = (const float*)d_in[0];
        z   = (const float*)d_in[1];
    }
    float* out = (float*)d_out;                  // [64,32,32] indices as float32

    e2_kernel<<<K_CODES, 32>>>(emb);
    zz_kernel<<<N_PTS / 256, 256>>>(z);
    dim3 grid(P_PER_B / TM, N_BATCH);            // (8, 64)
    vq_argmin_kernel<<<grid, 256>>>(z, emb, out);
}

// round 6
// speedup vs baseline: 2.8078x; 2.8078x over previous
#include <cuda_runtime.h>
#include <cuda_bf16.h>
#include <cstdint>
#include <cstddef>

// ---------------------------------------------------------------- constants
#define D_DIM   256
#define K_CODES 1024
#define P_PER_B 1024
#define N_BATCH 64
#define N_PTS   (N_BATCH * P_PER_B)    // 65536
#define MP      128                    // points per CTA
#define NTILE   64                     // codes per tile
#define TILES   (K_CODES / NTILE)      // 16
#define TAU     1e-3f
#define CAP     3000                   // candidate list capacity

// padded smem row: 256 bf16 + 8 pad = 264 units = 528 B (rotates banks by 4/row)
#define PITCH_B 528
#define A_ROW   528

#define OFF_A      0
#define OFF_B0     67584
#define OFF_B1     101376
#define OFF_E2S    135168
#define OFF_ROWMIN 139264
#define OFF_SLOT   139776
#define OFF_LIST   140800
#define OFF_CNT    164800
#define SMEM_TOTAL 164816

// ---------------------------------------------------------------- scratch
__device__ float g_e2[K_CODES];
__device__ float g_zz[N_PTS];
__device__ __align__(16) float    g_zt[(size_t)N_PTS * D_DIM];     // z transposed [p][d] fp32
__device__ __align__(16) uint16_t g_eb[(size_t)K_CODES * D_DIM];   // emb bf16 [k][d]

// ---------------------------------------------------------------- helpers
__device__ __forceinline__ uint32_t smem_u32(const void* p) {
    uint32_t a;
    asm("{ .reg .u64 t; cvta.to.shared.u64 t, %1; cvt.u32.u64 %0, t; }" : "=r"(a) : "l"(p));
    return a;
}
__device__ __forceinline__ void ldmatrix_x4(uint32_t& r0, uint32_t& r1,
                                            uint32_t& r2, uint32_t& r3, uint32_t a) {
    asm volatile("ldmatrix.sync.aligned.m8n8.x4.shared.b16 {%0,%1,%2,%3}, [%4];"
                 : "=r"(r0), "=r"(r1), "=r"(r2), "=r"(r3) : "r"(a));
}
__device__ __forceinline__ void mma_bf16(float* c, const uint32_t* a,
                                         uint32_t b0, uint32_t b1) {
    asm volatile(
        "mma.sync.aligned.m16n8k16.row.col.f32.bf16.bf16.f32 "
        "{%0,%1,%2,%3}, {%4,%5,%6,%7}, {%8,%9}, {%0,%1,%2,%3};"
        : "+f"(c[0]), "+f"(c[1]), "+f"(c[2]), "+f"(c[3])
        : "r"(a[0]), "r"(a[1]), "r"(a[2]), "r"(a[3]), "r"(b0), "r"(b1));
}
__device__ __forceinline__ void cp16(uint32_t dst, const void* src) {
    asm volatile("cp.async.cg.shared.global [%0], [%1], 16;" :: "r"(dst), "l"(src) : "memory");
}

// ---------------------------------------------------------------- prep
__global__ void e2_kernel(const float* __restrict__ emb) {
    int k = blockIdx.x, lane = threadIdx.x;
    const float* row = emb + (size_t)k * D_DIM;
    float s = 0.f;
    #pragma unroll
    for (int j = 0; j < D_DIM / 32; ++j) { float v = row[lane + 32 * j]; s = __fmaf_rn(v, v, s); }
    #pragma unroll
    for (int o = 16; o > 0; o >>= 1) s += __shfl_xor_sync(0xffffffffu, s, o);
    if (lane == 0) g_e2[k] = s;
}
__global__ void zz_kernel(const float* __restrict__ z) {
    int n = blockIdx.x * blockDim.x + threadIdx.x;
    int b = n >> 10, p = n & 1023;
    const float* zp = z + (size_t)b * D_DIM * P_PER_B + p;
    float s = 0.f;
    #pragma unroll 8
    for (int d = 0; d < D_DIM; ++d) { float v = zp[(size_t)d * P_PER_B]; s = __fmaf_rn(v, v, s); }
    g_zz[n] = s;
}
// z NCHW [b][d][p] -> g_zt [b*1024+p][d]
__global__ void prep_z_kernel(const float* __restrict__ z) {
    __shared__ float tile[32][33];
    int b = blockIdx.z, d0 = blockIdx.y * 32, p0 = blockIdx.x * 32;
    int tx = threadIdx.x, ty = threadIdx.y;          // (32,8)
    #pragma unroll
    for (int r = 0; r < 4; ++r)
        tile[ty + 8 * r][tx] = z[((size_t)b * D_DIM + d0 + ty + 8 * r) * P_PER_B + p0 + tx];
    __syncthreads();
    #pragma unroll
    for (int r = 0; r < 4; ++r) {
        int pl = ty + 8 * r;
        g_zt[((size_t)b * P_PER_B + p0 + pl) * D_DIM + d0 + tx] = tile[tx][pl];
    }
}
__global__ void prep_e_kernel(const float* __restrict__ emb) {
    int i = blockIdx.x * 256 + threadIdx.x;
    g_eb[i] = __bfloat16_as_ushort(__float2bfloat16(emb[i]));
}

// ---------------------------------------------------------------- main
__global__ void __launch_bounds__(128)
vq_hmma_kernel(const float* __restrict__ emb, float* __restrict__ out) {
    extern __shared__ __align__(16) char sm[];
    const uint32_t sb = smem_u32(sm);
    const int tid = threadIdx.x, w = tid >> 5, l = tid & 31;
    const int m_base = blockIdx.x * MP;

    unsigned long long* slot = reinterpret_cast<unsigned long long*>(sm + OFF_SLOT);
    uint2* list = reinterpret_cast<uint2*>(sm + OFF_LIST);
    int*   cnt  = reinterpret_cast<int*>(sm + OFF_CNT);
    float* e2s  = reinterpret_cast<float*>(sm + OFF_E2S);
    float* rowmin_s = reinterpret_cast<float*>(sm + OFF_ROWMIN);

    slot[tid] = ~0ull;
    if (tid == 0) *cnt = 0;
    #pragma unroll
    for (int i = 0; i < 8; ++i) e2s[tid + 128 * i] = g_e2[tid + 128 * i];

    // ---- A tile: g_zt fp32 -> smem bf16 [128][264]
    for (int q = tid; q < MP * 64; q += 128) {
        int row = q >> 6, seg = q & 63;
        float4 v = *reinterpret_cast<const float4*>(
            g_zt + ((size_t)(m_base + row)) * D_DIM + seg * 4);
        __nv_bfloat162 lo = __float22bfloat162_rn(make_float2(v.x, v.y));
        __nv_bfloat162 hi = __float22bfloat162_rn(make_float2(v.z, v.w));
        uint2 u = make_uint2(*reinterpret_cast<uint32_t*>(&lo),
                             *reinterpret_cast<uint32_t*>(&hi));
        *reinterpret_cast<uint2*>(sm + OFF_A + row * A_ROW + seg * 8) = u;
    }

    // ---- prologue: B tile 0
    {
        const char* src = reinterpret_cast<const char*>(g_eb);
        for (int q = tid; q < 2048; q += 128) {
            int row = q >> 5, off = q & 31;
            cp16(sb + OFF_B0 + row * PITCH_B + off * 16, src + row * 512 + off * 16);
        }
        asm volatile("cp.async.commit_group;" ::: "memory");
    }
    __syncthreads();

    float rowmin[2][2] = {{3.4e38f, 3.4e38f}, {3.4e38f, 3.4e38f}};

    for (int t = 0; t < TILES; ++t) {
        if (t + 1 < TILES) {
            const char* src = reinterpret_cast<const char*>(g_eb) + (size_t)(t + 1) * NTILE * 512;
            uint32_t dstb = sb + (((t + 1) & 1) ? OFF_B1 : OFF_B0);
            for (int q = tid; q < 2048; q += 128) {
                int row = q >> 5, off = q & 31;
                cp16(dstb + row * PITCH_B + off * 16, src + row * 512 + off * 16);
            }
            asm volatile("cp.async.commit_group;" ::: "memory");
            asm volatile("cp.async.wait_group 1;" ::: "memory");
        } else {
            asm volatile("cp.async.wait_group 0;" ::: "memory");
        }
        __syncthreads();

        const uint32_t Bb = sb + ((t & 1) ? OFF_B1 : OFF_B0);
        const uint32_t Ab = sb + OFF_A;

        float acc[2][8][4];
        #pragma unroll
        for (int mt = 0; mt < 2; ++mt)
            #pragma unroll
            for (int nt = 0; nt < 8; ++nt)
                #pragma unroll
                for (int c = 0; c < 4; ++c) acc[mt][nt][c] = 0.f;

        #pragma unroll
        for (int ks = 0; ks < 16; ++ks) {
            uint32_t a[2][4];
            #pragma unroll
            for (int mt = 0; mt < 2; ++mt) {
                uint32_t addr = Ab + (w * 32 + mt * 16 + (l & 15)) * A_ROW
                              + (ks * 16 + ((l >> 4) & 1) * 8) * 2;
                ldmatrix_x4(a[mt][0], a[mt][1], a[mt][2], a[mt][3], addr);
            }
            uint32_t b[4][4];
            #pragma unroll
            for (int j = 0; j < 4; ++j) {
                uint32_t addr = Bb + (j * 16 + ((l >> 4) & 1) * 8 + (l & 7)) * PITCH_B
                              + (ks * 16 + ((l >> 3) & 1) * 8) * 2;
                ldmatrix_x4(b[j][0], b[j][1], b[j][2], b[j][3], addr);
            }
            #pragma unroll
            for (int mt = 0; mt < 2; ++mt)
                #pragma unroll
                for (int nt = 0; nt < 8; ++nt)
                    mma_bf16(acc[mt][nt], a[mt],
                             b[nt >> 1][(nt & 1) * 2], b[nt >> 1][(nt & 1) * 2 + 1]);
        }

        // ---- epilogue: scores, running row-min, candidate collection
        const int n0 = t * NTILE;
        float e2v[8][2];
        #pragma unroll
        for (int nt = 0; nt < 8; ++nt) {
            e2v[nt][0] = e2s[n0 + nt * 8 + (l & 3) * 2];
            e2v[nt][1] = e2s[n0 + nt * 8 + (l & 3) * 2 + 1];
        }
        #pragma unroll
        for (int mt = 0; mt < 2; ++mt)
            #pragma unroll
            for (int nt = 0; nt < 8; ++nt)
                #pragma unroll
                for (int c = 0; c < 4; ++c) {
                    float s = __fmaf_rn(-2.f, acc[mt][nt][c], e2v[nt][c & 1]);
                    rowmin[mt][c >> 1] = fminf(rowmin[mt][c >> 1], s);
                }
        // quad-reduce row minima (lanes l^1, l^2 share the same rows)
        #pragma unroll
        for (int mt = 0; mt < 2; ++mt)
            #pragma unroll
            for (int h = 0; h < 2; ++h) {
                float v = rowmin[mt][h];
                v = fminf(v, __shfl_xor_sync(0xffffffffu, v, 1));
                v = fminf(v, __shfl_xor_sync(0xffffffffu, v, 2));
                rowmin[mt][h] = v;
            }
        // collect candidates vs current running min
        #pragma unroll
        for (int mt = 0; mt < 2; ++mt)
            #pragma unroll
            for (int nt = 0; nt < 8; ++nt)
                #pragma unroll
                for (int c = 0; c < 4; ++c) {
                    float s = __fmaf_rn(-2.f, acc[mt][nt][c], e2v[nt][c & 1]);
                    if (s <= rowmin[mt][c >> 1] + TAU) {
                        int row  = w * 32 + mt * 16 + (l >> 2) + (c >> 1) * 8;
                        int code = n0 + nt * 8 + (l & 3) * 2 + (c & 1);
                        int pos = atomicAdd(cnt, 1);
                        if (pos < CAP)
                            list[pos] = make_uint2((uint32_t)(row << 10) | code,
                                                   __float_as_uint(s));
                    }
                }
        __syncthreads();   // all reads of this B buffer done before reuse
    }

    // final row minima to smem (lane 0 of each quad owns the value)
    if ((l & 3) == 0) {
        #pragma unroll
        for (int mt = 0; mt < 2; ++mt)
            #pragma unroll
            for (int h = 0; h < 2; ++h)
                rowmin_s[w * 32 + mt * 16 + (l >> 2) + h * 8] = rowmin[mt][h];
    }
    __syncthreads();

    // ---- exact fp32 refine of surviving candidates
    int total = *cnt; if (total > CAP) total = CAP;
    for (int i = tid; i < total; i += 128) {
        uint2 ent = list[i];
        int row = ent.x >> 10, code = ent.x & 1023;
        if (__uint_as_float(ent.y) > rowmin_s[row] + TAU) continue;
        const float* zr = g_zt + (size_t)(m_base + row) * D_DIM;
        const float* er = emb + (size_t)code * D_DIM;
        float a0 = 0.f, a1 = 0.f, a2 = 0.f, a3 = 0.f;
        #pragma unroll 4
        for (int d = 0; d < D_DIM; d += 16) {
            float4 z0 = *reinterpret_cast<const float4*>(zr + d);
            float4 e0 = *reinterpret_cast<const float4*>(er + d);
            float4 z1 = *reinterpret_cast<const float4*>(zr + d + 4);
            float4 e1 = *reinterpret_cast<const float4*>(er + d + 4);
            float4 z2 = *reinterpret_cast<const float4*>(zr + d + 8);
            float4 e2_ = *reinterpret_cast<const float4*>(er + d + 8);
            float4 z3 = *reinterpret_cast<const float4*>(zr + d + 12);
            float4 e3 = *reinterpret_cast<const float4*>(er + d + 12);
            a0 = __fmaf_rn(z0.x, e0.x, a0); a0 = __fmaf_rn(z0.y, e0.y, a0);
            a0 = __fmaf_rn(z0.z, e0.z, a0); a0 = __fmaf_rn(z0.w, e0.w, a0);
            a1 = __fmaf_rn(z1.x, e1.x, a1); a1 = __fmaf_rn(z1.y, e1.y, a1);
            a1 = __fmaf_rn(z1.z, e1.z, a1); a1 = __fmaf_rn(z1.w, e1.w, a1);
            a2 = __fmaf_rn(z2.x, e2_.x, a2); a2 = __fmaf_rn(z2.y, e2_.y, a2);
            a2 = __fmaf_rn(z2.z, e2_.z, a2); a2 = __fmaf_rn(z2.w, e2_.w, a2);
            a3 = __fmaf_rn(z3.x, e3.x, a3); a3 = __fmaf_rn(z3.y, e3.y, a3);
            a3 = __fmaf_rn(z3.z, e3.z, a3); a3 = __fmaf_rn(z3.w, e3.w, a3);
        }
        float dot = (a0 + a1) + (a2 + a3);
        float q = __fadd_rn(__fmaf_rn(-2.f, dot, g_zz[m_base + row]), g_e2[code]);
        unsigned long long key = ((unsigned long long)__float_as_uint(q) << 32) | (uint32_t)code;
        atomicMin(&slot[row], key);
    }
    __syncthreads();

    out[m_base + tid] = (float)(uint32_t)(slot[tid] & 0xffffffffull);
}

// ---------------------------------------------------------------- launch
extern "C" void kernel_launch(void* const* d_in, const int* in_sizes, int n_in,
                              void* d_out, int out_size) {
    const float* z   = (const float*)d_in[0];
    const float* emb = (const float*)d_in[1];
    if (n_in >= 2 && in_sizes[0] == K_CODES * D_DIM) {
        emb = (const float*)d_in[0];
        z   = (const float*)d_in[1];
    }
    float* out = (float*)d_out;

    static int smem_set = 0;
    if (!smem_set) {
        cudaFuncSetAttribute(vq_hmma_kernel,
                             cudaFuncAttributeMaxDynamicSharedMemorySize, SMEM_TOTAL);
        smem_set = 1;
    }

    e2_kernel<<<K_CODES, 32>>>(emb);
    zz_kernel<<<N_PTS / 256, 256>>>(z);
    prep_z_kernel<<<dim3(32, 8, N_BATCH), dim3(32, 8)>>>(z);
    prep_e_kernel<<<K_CODES, 256>>>(emb);
    vq_hmma_kernel<<<N_PTS / MP, 128, SMEM_TOTAL>>>(emb, out);
}